// round 1
// baseline (speedup 1.0000x reference)
#include <cuda_runtime.h>
#include <math.h>

#define M_ROWS 8192
#define N_COLS 16384
#define K_DIM  512
#define BM 128
#define BN 128
#define BK 16
#define TM 8
#define TN 8
#define PAD 4
#define N_SLICES 32
#define SLICE_W (N_COLS / N_SLICES)   /* 512 */
#define TOPK 9
#define NBATCH 8

__device__ unsigned g_row_min[M_ROWS];
__device__ float    g_fnorm[M_ROWS];
__device__ float    g_mnorm[N_COLS];
__device__ int      g_best[NBATCH];

// ---------------------------------------------------------------------------
__global__ void init_kernel() {
    int i = blockIdx.x * blockDim.x + threadIdx.x;
    if (i < M_ROWS) g_row_min[i] = 0x7f800000u;  // +inf
}

// ---------------------------------------------------------------------------
// One warp per vector: squared L2 norms of feature rows and memory-bank rows.
__global__ void norms_kernel(const float* __restrict__ fv,
                             const float* __restrict__ mb) {
    int gw   = (blockIdx.x * blockDim.x + threadIdx.x) >> 5;
    int lane = threadIdx.x & 31;
    const float4* src;
    if (gw < M_ROWS)                 src = (const float4*)(fv + (size_t)gw * K_DIM);
    else if (gw < M_ROWS + N_COLS)   src = (const float4*)(mb + (size_t)(gw - M_ROWS) * K_DIM);
    else return;
    float s = 0.f;
    #pragma unroll
    for (int i = lane; i < K_DIM / 4; i += 32) {
        float4 v = src[i];
        s += v.x * v.x + v.y * v.y + v.z * v.z + v.w * v.w;
    }
    #pragma unroll
    for (int o = 16; o; o >>= 1) s += __shfl_xor_sync(0xffffffffu, s, o);
    if (lane == 0) {
        if (gw < M_ROWS) g_fnorm[gw] = s;
        else             g_mnorm[gw - M_ROWS] = s;
    }
}

// ---------------------------------------------------------------------------
// Register-tiled fp32 GEMM computing distances with fused per-row min.
// Grid: (N_SLICES, M_ROWS/BM). Each CTA: 128 rows x (SLICE_W) cols.
__global__ void __launch_bounds__(256, 2)
dist_min_kernel(const float* __restrict__ A, const float* __restrict__ Bm) {
    __shared__ float As[BK][BM + PAD];
    __shared__ float Bs[BK][BN + PAD];

    const int tid = threadIdx.x;
    const int tx  = tid & 15;
    const int ty  = tid >> 4;
    const int m0  = blockIdx.y * BM;
    const int n_base = blockIdx.x * SLICE_W;

    float fn[TM];
    #pragma unroll
    for (int i = 0; i < TM; i++) fn[i] = g_fnorm[m0 + ty * TM + i];

    float rmin[TM];
    #pragma unroll
    for (int i = 0; i < TM; i++) rmin[i] = 3.402823e38f;

    // float4-granular load mapping: 512 float4 per tile, 2 per thread
    const int p0 = tid;        const int r0 = p0 >> 2, q0 = p0 & 3;
    const int p1 = tid + 256;  const int r1 = p1 >> 2, q1 = p1 & 3;

    for (int t = 0; t < SLICE_W / BN; t++) {
        const int n0 = n_base + t * BN;

        float acc[TM][TN];
        #pragma unroll
        for (int i = 0; i < TM; i++)
            #pragma unroll
            for (int j = 0; j < TN; j++) acc[i][j] = 0.f;

        for (int k0 = 0; k0 < K_DIM; k0 += BK) {
            // ---- load A/B tiles (transposed into shared) ----
            {
                float4 va = *(const float4*)(A  + (size_t)(m0 + r0) * K_DIM + k0 + q0 * 4);
                As[q0*4+0][r0] = va.x; As[q0*4+1][r0] = va.y;
                As[q0*4+2][r0] = va.z; As[q0*4+3][r0] = va.w;
                float4 vb = *(const float4*)(A  + (size_t)(m0 + r1) * K_DIM + k0 + q1 * 4);
                As[q1*4+0][r1] = vb.x; As[q1*4+1][r1] = vb.y;
                As[q1*4+2][r1] = vb.z; As[q1*4+3][r1] = vb.w;
                float4 wa = *(const float4*)(Bm + (size_t)(n0 + r0) * K_DIM + k0 + q0 * 4);
                Bs[q0*4+0][r0] = wa.x; Bs[q0*4+1][r0] = wa.y;
                Bs[q0*4+2][r0] = wa.z; Bs[q0*4+3][r0] = wa.w;
                float4 wb = *(const float4*)(Bm + (size_t)(n0 + r1) * K_DIM + k0 + q1 * 4);
                Bs[q1*4+0][r1] = wb.x; Bs[q1*4+1][r1] = wb.y;
                Bs[q1*4+2][r1] = wb.z; Bs[q1*4+3][r1] = wb.w;
            }
            __syncthreads();

            #pragma unroll
            for (int kk = 0; kk < BK; kk++) {
                float4 a0 = *(const float4*)&As[kk][ty * TM];
                float4 a1 = *(const float4*)&As[kk][ty * TM + 4];
                float4 b0 = *(const float4*)&Bs[kk][tx * TN];
                float4 b1 = *(const float4*)&Bs[kk][tx * TN + 4];
                float a[8] = {a0.x, a0.y, a0.z, a0.w, a1.x, a1.y, a1.z, a1.w};
                float b[8] = {b0.x, b0.y, b0.z, b0.w, b1.x, b1.y, b1.z, b1.w};
                #pragma unroll
                for (int i = 0; i < TM; i++)
                    #pragma unroll
                    for (int j = 0; j < TN; j++)
                        acc[i][j] = fmaf(a[i], b[j], acc[i][j]);
            }
            __syncthreads();
        }

        // ---- epilogue: distance + per-row min over this tile ----
        float mn[TN];
        #pragma unroll
        for (int j = 0; j < TN; j++) mn[j] = g_mnorm[n0 + tx * TN + j];
        #pragma unroll
        for (int i = 0; i < TM; i++) {
            #pragma unroll
            for (int j = 0; j < TN; j++) {
                float d = fn[i] + mn[j] - 2.0f * acc[i][j];
                d = fmaxf(d, 0.0f);
                rmin[i] = fminf(rmin[i], d);
            }
        }
    }

    // reduce row-min across the 16 tx lanes (xor<16 stays within same ty)
    #pragma unroll
    for (int i = 0; i < TM; i++) {
        float v = rmin[i];
        #pragma unroll
        for (int o = 1; o < 16; o <<= 1)
            v = fminf(v, __shfl_xor_sync(0xffffffffu, v, o));
        if (tx == 0)
            atomicMin(&g_row_min[m0 + ty * TM + i], __float_as_uint(v));
    }
}

// ---------------------------------------------------------------------------
// Per batch: pixel scores = sqrt(min dist); argmax with first-index tie-break.
__global__ void pixel_kernel(float* __restrict__ out_pixel) {
    __shared__ float sv[1024];
    __shared__ int   si[1024];
    int b = blockIdx.x;
    int i = threadIdx.x;
    int r = b * 1024 + i;
    float v = sqrtf(__uint_as_float(g_row_min[r]));
    out_pixel[r] = v;
    sv[i] = v; si[i] = i;
    __syncthreads();
    for (int s = 512; s > 0; s >>= 1) {
        if (i < s) {
            float a = sv[i], c = sv[i + s];
            int ia = si[i], ic = si[i + s];
            if (c > a || (c == a && ic < ia)) { sv[i] = c; si[i] = ic; }
        }
        __syncthreads();
    }
    if (i == 0) g_best[b] = b * 1024 + si[0];
}

// ---------------------------------------------------------------------------
// For the 8 selected rows only: recompute all 16384 distances, take top-9
// smallest, then image_score = s0 * (1 - softmax(s)[0]).
__global__ void image_kernel(const float* __restrict__ fv,
                             const float* __restrict__ mb,
                             float* __restrict__ out_img) {
    __shared__ float f[K_DIM];
    __shared__ float warp_top[8][TOPK];
    int b   = blockIdx.x;
    int tid = threadIdx.x;
    int row = g_best[b];
    for (int i = tid; i < K_DIM; i += 256) f[i] = fv[(size_t)row * K_DIM + i];
    __syncthreads();
    float fn = g_fnorm[row];

    float t[TOPK];
    #pragma unroll
    for (int j = 0; j < TOPK; j++) t[j] = 3.402823e38f;

    const float4* f4 = (const float4*)f;
    for (int n = tid; n < N_COLS; n += 256) {
        const float4* m4 = (const float4*)(mb + (size_t)n * K_DIM);
        float s0 = 0.f, s1 = 0.f, s2 = 0.f, s3 = 0.f;
        #pragma unroll 4
        for (int k = 0; k < K_DIM / 4; k++) {
            float4 mv = m4[k]; float4 fx = f4[k];
            s0 = fmaf(mv.x, fx.x, s0);
            s1 = fmaf(mv.y, fx.y, s1);
            s2 = fmaf(mv.z, fx.z, s2);
            s3 = fmaf(mv.w, fx.w, s3);
        }
        float d = fn + g_mnorm[n] - 2.0f * ((s0 + s1) + (s2 + s3));
        d = fmaxf(d, 0.0f);
        if (d < t[TOPK - 1]) {
            t[TOPK - 1] = d;
            #pragma unroll
            for (int j = TOPK - 1; j > 0; j--)
                if (t[j] < t[j - 1]) { float tmp = t[j]; t[j] = t[j - 1]; t[j - 1] = tmp; }
        }
    }

    // warp-level merge of sorted top-9 lists
    #pragma unroll
    for (int off = 1; off < 32; off <<= 1) {
        float o[TOPK];
        #pragma unroll
        for (int j = 0; j < TOPK; j++) o[j] = __shfl_xor_sync(0xffffffffu, t[j], off);
        #pragma unroll
        for (int j = 0; j < TOPK; j++) {
            float v = o[j];
            if (v < t[TOPK - 1]) {
                t[TOPK - 1] = v;
                #pragma unroll
                for (int q = TOPK - 1; q > 0; q--)
                    if (t[q] < t[q - 1]) { float tmp = t[q]; t[q] = t[q - 1]; t[q - 1] = tmp; }
            }
        }
    }

    int lane = tid & 31, w = tid >> 5;
    if (lane == 0) {
        #pragma unroll
        for (int j = 0; j < TOPK; j++) warp_top[w][j] = t[j];
    }
    __syncthreads();

    if (tid == 0) {
        float m[TOPK];
        #pragma unroll
        for (int j = 0; j < TOPK; j++) m[j] = warp_top[0][j];
        for (int w2 = 1; w2 < 8; w2++) {
            for (int j = 0; j < TOPK; j++) {
                float v = warp_top[w2][j];
                if (v < m[TOPK - 1]) {
                    m[TOPK - 1] = v;
                    for (int q = TOPK - 1; q > 0; q--)
                        if (m[q] < m[q - 1]) { float tmp = m[q]; m[q] = m[q - 1]; m[q - 1] = tmp; }
                }
            }
        }
        float s[TOPK];
        for (int j = 0; j < TOPK; j++) s[j] = sqrtf(m[j]);
        float mx = s[TOPK - 1];          // largest (ascending order)
        float sum = 0.f, e0 = 0.f;
        for (int j = 0; j < TOPK; j++) {
            float e = expf(s[j] - mx);
            sum += e;
            if (j == 0) e0 = e;
        }
        out_img[b] = s[0] * (1.0f - e0 / sum);
    }
}

// ---------------------------------------------------------------------------
extern "C" void kernel_launch(void* const* d_in, const int* in_sizes, int n_in,
                              void* d_out, int out_size) {
    const float* fv = (const float*)d_in[0];   // feature_batch (8,32,32,512) -> (8192,512)
    const float* mb = (const float*)d_in[1];   // mb (16384,512)
    float* out = (float*)d_out;                // [0..8191] pixel, [8192..8199] image

    init_kernel<<<(M_ROWS + 255) / 256, 256>>>();

    int total_warps = M_ROWS + N_COLS;
    int norm_blocks = (total_warps * 32 + 255) / 256;
    norms_kernel<<<norm_blocks, 256>>>(fv, mb);

    dim3 grid(N_SLICES, M_ROWS / BM);
    dist_min_kernel<<<grid, 256>>>(fv, mb);

    pixel_kernel<<<NBATCH, 1024>>>(out);
    image_kernel<<<NBATCH, 256>>>(fv, mb, out + M_ROWS);
}

// round 7
// speedup vs baseline: 2.7857x; 2.7857x over previous
#include <cuda_runtime.h>
#include <cuda_bf16.h>
#include <math.h>
#include <stdint.h>

#define M_ROWS 8192
#define N_COLS 16384
#define K_DIM  512
#define BM 128
#define BN 256
#define BK 64
#define THREADS 512
#define TOPK 9
#define NBATCH 8
#define NSLICE 32
#define SLICE_W (N_COLS / NSLICE)
#define M_TILES (M_ROWS / BM)            /* 64 */
#define N_TILES (N_COLS / BN)            /* 64 */
#define KSTAGES (K_DIM / BK)             /* 8 */
#define MAXCAND 1024
#define CSLOTS  32
#define CAND_MARGIN 0.99f

#define A_BYTES (BM * BK * 2)            /* 16384 */
#define B_BYTES (BN * BK * 2)            /* 32768 */
#define SM_A(i)  ((i) * A_BYTES)
#define SM_B(i)  (3 * A_BYTES + (i) * B_BYTES)
#define SM_MN    (3 * A_BYTES + 3 * B_BYTES)   /* 147456 */
#define SMEM_SIZE (SM_MN + BN * 4)

__device__ __align__(16) __nv_bfloat16 g_fb[(size_t)M_ROWS * K_DIM];
__device__ __align__(16) __nv_bfloat16 g_mbb[(size_t)N_COLS * K_DIM];
__device__ float    g_fnorm[M_ROWS];
__device__ float    g_mnorm[N_COLS];
__device__ unsigned g_row_min[M_ROWS];
__device__ float    g_pmax[NBATCH];
__device__ int      g_cand_cnt[NBATCH];
__device__ int      g_cand_row[NBATCH][MAXCAND];
__device__ unsigned g_cand_min[NBATCH][MAXCAND];
__device__ int      g_best[NBATCH];
__device__ float    g_part[NBATCH * NSLICE * TOPK];

/* ---------------- PTX helpers ---------------- */
__device__ __forceinline__ uint32_t smem_u32(const void* p) {
    uint32_t a;
    asm("{ .reg .u64 t; cvta.to.shared.u64 t, %1; cvt.u32.u64 %0, t; }" : "=r"(a) : "l"(p));
    return a;
}
__device__ __forceinline__ void cp_async16(uint32_t dst, const void* src) {
    asm volatile("cp.async.cg.shared.global [%0], [%1], 16;" :: "r"(dst), "l"(src) : "memory");
}
__device__ __forceinline__ void cp_commit() { asm volatile("cp.async.commit_group;" ::: "memory"); }
template <int N> __device__ __forceinline__ void cp_wait() {
    asm volatile("cp.async.wait_group %0;" :: "n"(N) : "memory");
}
__device__ __forceinline__ void ldsm4(uint32_t* r, uint32_t addr) {
    asm volatile("ldmatrix.sync.aligned.m8n8.x4.shared.b16 {%0,%1,%2,%3}, [%4];"
                 : "=r"(r[0]), "=r"(r[1]), "=r"(r[2]), "=r"(r[3]) : "r"(addr));
}
__device__ __forceinline__ void mma16816(float* d, const uint32_t* a, uint32_t b0, uint32_t b1) {
    asm volatile("mma.sync.aligned.m16n8k16.row.col.f32.bf16.bf16.f32 "
                 "{%0,%1,%2,%3}, {%4,%5,%6,%7}, {%8,%9}, {%0,%1,%2,%3};"
                 : "+f"(d[0]), "+f"(d[1]), "+f"(d[2]), "+f"(d[3])
                 : "r"(a[0]), "r"(a[1]), "r"(a[2]), "r"(a[3]), "r"(b0), "r"(b1));
}

/* ---------------- small kernels ---------------- */
__global__ void init_kernel() {
    int i = blockIdx.x * blockDim.x + threadIdx.x;
    if (i < M_ROWS) g_row_min[i] = 0x7f800000u;
    if (i < NBATCH) g_cand_cnt[i] = 0;
    if (i < NBATCH * MAXCAND) g_cand_min[i / MAXCAND][i % MAXCAND] = 0x7f800000u;
}

// one warp per row: fp32 norm + bf16 conversion
__global__ void prep_kernel(const float* __restrict__ fv, const float* __restrict__ mb) {
    int gw   = (blockIdx.x * blockDim.x + threadIdx.x) >> 5;
    int lane = threadIdx.x & 31;
    const float* src; __nv_bfloat16* dst; float* nout;
    if (gw < M_ROWS) {
        src = fv + (size_t)gw * K_DIM; dst = g_fb + (size_t)gw * K_DIM; nout = &g_fnorm[gw];
    } else if (gw < M_ROWS + N_COLS) {
        int r = gw - M_ROWS;
        src = mb + (size_t)r * K_DIM; dst = g_mbb + (size_t)r * K_DIM; nout = &g_mnorm[r];
    } else return;
    float s = 0.f;
    #pragma unroll
    for (int i = lane; i < K_DIM / 4; i += 32) {
        float4 v = ((const float4*)src)[i];
        s += v.x * v.x + v.y * v.y + v.z * v.z + v.w * v.w;
        __nv_bfloat162 lo = __floats2bfloat162_rn(v.x, v.y);
        __nv_bfloat162 hi = __floats2bfloat162_rn(v.z, v.w);
        uint2 pk; pk.x = *(uint32_t*)&lo; pk.y = *(uint32_t*)&hi;
        ((uint2*)dst)[i] = pk;
    }
    #pragma unroll
    for (int o = 16; o; o >>= 1) s += __shfl_xor_sync(0xffffffffu, s, o);
    if (lane == 0) *nout = s;
}

/* ---------------- GEMM + fused row-min (mma.sync bf16) ---------------- */
__device__ __forceinline__ void load_stage(uint32_t sb, int buf,
                                           const __nv_bfloat16* Ap,
                                           const __nv_bfloat16* Bp,
                                           int kc, int tid) {
    uint32_t a0 = sb + SM_A(buf);
    uint32_t b0 = sb + SM_B(buf);
    #pragma unroll
    for (int j = 0; j < 2; j++) {
        int q = tid + j * THREADS, r = q >> 3, c = q & 7;
        uint32_t off = (uint32_t)((r >> 3) * 1024 + (r & 7) * 128 + ((c ^ (r & 7)) << 4));
        cp_async16(a0 + off, Ap + (size_t)r * K_DIM + kc + c * 8);
    }
    #pragma unroll
    for (int j = 0; j < 4; j++) {
        int q = tid + j * THREADS, r = q >> 3, c = q & 7;
        uint32_t off = (uint32_t)((r >> 3) * 1024 + (r & 7) * 128 + ((c ^ (r & 7)) << 4));
        cp_async16(b0 + off, Bp + (size_t)r * K_DIM + kc + c * 8);
    }
    cp_commit();
}

__global__ void __launch_bounds__(THREADS, 1)
gemm_min_kernel() {
    extern __shared__ char smem[];
    uint32_t sb = smem_u32(smem);
    float* mn_s = (float*)(smem + SM_MN);

    const int tid  = threadIdx.x;
    const int lane = tid & 31;
    const int wid  = tid >> 5;
    const int wm   = wid >> 3;
    const int wn   = wid & 7;

    const int tile = blockIdx.x;
    const int mt = tile >> 6;
    const int nt = tile & 63;
    const __nv_bfloat16* Ap = g_fb  + (size_t)mt * BM * K_DIM;
    const __nv_bfloat16* Bp = g_mbb + (size_t)nt * BN * K_DIM;

    if (tid < BN / 2) {
        mn_s[tid * 2]     = g_mnorm[nt * BN + tid * 2];
        mn_s[tid * 2 + 1] = g_mnorm[nt * BN + tid * 2 + 1];
    }

    uint32_t a_base[4], b_base[2];
    uint32_t a_xr, b_xr;
    {
        int rA = wm * 64 + (lane & 15);
        a_xr = (uint32_t)(rA & 7);
        #pragma unroll
        for (int mi = 0; mi < 4; mi++) {
            int r = rA + mi * 16;
            a_base[mi] = (uint32_t)((r >> 3) * 1024 + (r & 7) * 128);
        }
        int rB = wn * 32 + (lane & 7) + ((lane >> 4) << 3);
        b_xr = (uint32_t)(rB & 7);
        #pragma unroll
        for (int nb = 0; nb < 2; nb++) {
            int r = rB + nb * 16;
            b_base[nb] = (uint32_t)((r >> 3) * 1024 + (r & 7) * 128);
        }
    }
    const uint32_t a_csel = (uint32_t)(lane >> 4);
    const uint32_t b_csel = (uint32_t)((lane >> 3) & 1);

    float acc[4][4][4];
    #pragma unroll
    for (int mi = 0; mi < 4; mi++)
        #pragma unroll
        for (int ni = 0; ni < 4; ni++)
            #pragma unroll
            for (int k = 0; k < 4; k++) acc[mi][ni][k] = 0.f;

    load_stage(sb, 0, Ap, Bp, 0, tid);
    load_stage(sb, 1, Ap, Bp, BK, tid);

    #pragma unroll
    for (int s = 0; s < KSTAGES; s++) {
        if (s < KSTAGES - 1) cp_wait<1>(); else cp_wait<0>();
        __syncthreads();
        if (s + 2 < KSTAGES)
            load_stage(sb, (s + 2) % 3, Ap, Bp, (s + 2) * BK, tid);

        const int buf = s % 3;
        const uint32_t ab = sb + SM_A(buf);
        const uint32_t bb = sb + SM_B(buf);
        #pragma unroll
        for (int ks = 0; ks < 4; ks++) {
            uint32_t a[4][4], bf[2][4];
            const uint32_t ca = (uint32_t)(ks * 2) + a_csel;
            const uint32_t cb = (uint32_t)(ks * 2) + b_csel;
            #pragma unroll
            for (int mi = 0; mi < 4; mi++)
                ldsm4(a[mi], ab + a_base[mi] + ((ca ^ a_xr) << 4));
            #pragma unroll
            for (int nb = 0; nb < 2; nb++)
                ldsm4(bf[nb], bb + b_base[nb] + ((cb ^ b_xr) << 4));
            #pragma unroll
            for (int mi = 0; mi < 4; mi++)
                #pragma unroll
                for (int ni = 0; ni < 4; ni++)
                    mma16816(acc[mi][ni], a[mi], bf[ni >> 1][(ni & 1) * 2],
                             bf[ni >> 1][(ni & 1) * 2 + 1]);
        }
        __syncthreads();
    }

    const int q  = lane & 3;
    const int gr = lane >> 2;
    #pragma unroll
    for (int mi = 0; mi < 4; mi++) {
        #pragma unroll
        for (int h = 0; h < 2; h++) {
            float vmin = 3.402823e38f;
            #pragma unroll
            for (int ni = 0; ni < 4; ni++) {
                int col = wn * 32 + ni * 8 + q * 2;
                float v0 = fmaf(-2.0f, acc[mi][ni][h * 2],     mn_s[col]);
                float v1 = fmaf(-2.0f, acc[mi][ni][h * 2 + 1], mn_s[col + 1]);
                vmin = fminf(vmin, fminf(v0, v1));
            }
            vmin = fminf(vmin, __shfl_xor_sync(0xffffffffu, vmin, 1));
            vmin = fminf(vmin, __shfl_xor_sync(0xffffffffu, vmin, 2));
            if (q == 0) {
                int row = mt * BM + wm * 64 + mi * 16 + h * 8 + gr;
                float d = fmaxf(g_fnorm[row] + vmin, 0.0f);
                atomicMin(&g_row_min[row], __float_as_uint(d));
            }
        }
    }
}

/* ---------------- tails ---------------- */
__global__ void pixel_kernel(float* __restrict__ out_pixel) {
    __shared__ float sv[1024];
    int b = blockIdx.x, i = threadIdx.x;
    int r = b * 1024 + i;
    float v = sqrtf(__uint_as_float(g_row_min[r]));
    out_pixel[r] = v;
    sv[i] = v;
    __syncthreads();
    for (int s = 512; s > 0; s >>= 1) {
        if (i < s) sv[i] = fmaxf(sv[i], sv[i + s]);
        __syncthreads();
    }
    if (i == 0) g_pmax[b] = sv[0];
}

__global__ void candidate_kernel() {
    int b = blockIdx.x, i = threadIdx.x;
    int r = b * 1024 + i;
    float v = sqrtf(__uint_as_float(g_row_min[r]));
    if (v >= g_pmax[b] * CAND_MARGIN) {
        int slot = atomicAdd(&g_cand_cnt[b], 1);
        g_cand_row[b][slot] = r;       // slot < 1024 always
    }
}

// exact fp32 min distance per candidate (sequential FMA chains == round-1 arithmetic)
__global__ void exact_cand(const float* __restrict__ fv, const float* __restrict__ mb) {
    int slice = blockIdx.x, cslot = blockIdx.y, b = blockIdx.z;
    int cnt = g_cand_cnt[b];
    if (cnt > MAXCAND) cnt = MAXCAND;
    __shared__ float f[K_DIM];
    __shared__ float wmin[4];
    int tid = threadIdx.x;

    for (int c = cslot; c < cnt; c += CSLOTS) {
        int row = g_cand_row[b][c];
        __syncthreads();
        for (int i = tid; i < K_DIM; i += 128) f[i] = fv[(size_t)row * K_DIM + i];
        __syncthreads();
        float fn = g_fnorm[row];

        int n0 = slice * SLICE_W + tid;
        const float* m0 = mb + (size_t)n0 * K_DIM;
        const float* m1 = m0 + (size_t)128 * K_DIM;
        const float* m2 = m1 + (size_t)128 * K_DIM;
        const float* m3 = m2 + (size_t)128 * K_DIM;
        float a0 = 0.f, a1 = 0.f, a2 = 0.f, a3 = 0.f;
        for (int k = 0; k < K_DIM; k++) {
            float fk = f[k];
            a0 = fmaf(fk, __ldg(m0 + k), a0);
            a1 = fmaf(fk, __ldg(m1 + k), a1);
            a2 = fmaf(fk, __ldg(m2 + k), a2);
            a3 = fmaf(fk, __ldg(m3 + k), a3);
        }
        float d0 = fmaxf(fn + g_mnorm[n0]       - 2.0f * a0, 0.0f);
        float d1 = fmaxf(fn + g_mnorm[n0 + 128] - 2.0f * a1, 0.0f);
        float d2 = fmaxf(fn + g_mnorm[n0 + 256] - 2.0f * a2, 0.0f);
        float d3 = fmaxf(fn + g_mnorm[n0 + 384] - 2.0f * a3, 0.0f);
        float vmin = fminf(fminf(d0, d1), fminf(d2, d3));

        #pragma unroll
        for (int o = 16; o; o >>= 1)
            vmin = fminf(vmin, __shfl_xor_sync(0xffffffffu, vmin, o));
        if ((tid & 31) == 0) wmin[tid >> 5] = vmin;
        __syncthreads();
        if (tid == 0) {
            float m = fminf(fminf(wmin[0], wmin[1]), fminf(wmin[2], wmin[3]));
            atomicMin(&g_cand_min[b][c], __float_as_uint(m));
        }
    }
}

// exact argmax over candidates (first-index tie-break)
__global__ void argmax_refine() {
    int b = threadIdx.x;
    if (b >= NBATCH) return;
    int cnt = g_cand_cnt[b];
    if (cnt > MAXCAND) cnt = MAXCAND;
    float best_v = -1.f;
    int best_r = 0x7fffffff;
    for (int c = 0; c < cnt; c++) {
        float v = sqrtf(__uint_as_float(g_cand_min[b][c]));
        int r = g_cand_row[b][c];
        if (v > best_v || (v == best_v && r < best_r)) { best_v = v; best_r = r; }
    }
    g_best[b] = best_r;
}

__device__ __forceinline__ void insert9(float* t, float v) {
    if (v < t[TOPK - 1]) {
        t[TOPK - 1] = v;
        #pragma unroll
        for (int j = TOPK - 1; j > 0; j--)
            if (t[j] < t[j - 1]) { float tmp = t[j]; t[j] = t[j - 1]; t[j - 1] = tmp; }
    }
}

// CORRECT warp merge: snapshot ALL partner values BEFORE inserting any.
__device__ __forceinline__ void warp_merge9(float* t) {
    #pragma unroll
    for (int off = 1; off < 32; off <<= 1) {
        float o[TOPK];
        #pragma unroll
        for (int j = 0; j < TOPK; j++) o[j] = __shfl_xor_sync(0xffffffffu, t[j], off);
        #pragma unroll
        for (int j = 0; j < TOPK; j++) insert9(t, o[j]);
    }
}

__global__ void image_partial(const float* __restrict__ fv, const float* __restrict__ mb) {
    __shared__ float f[K_DIM];
    __shared__ float wt[4][TOPK];
    int slice = blockIdx.x, b = blockIdx.y;
    int tid = threadIdx.x;
    int row = g_best[b];
    for (int i = tid; i < K_DIM; i += 128) f[i] = fv[(size_t)row * K_DIM + i];
    __syncthreads();
    float fn = g_fnorm[row];

    float t[TOPK];
    #pragma unroll
    for (int j = 0; j < TOPK; j++) t[j] = 3.402823e38f;

    const float4* f4 = (const float4*)f;
    for (int nl = tid; nl < SLICE_W; nl += 128) {
        int n = slice * SLICE_W + nl;
        const float4* m4 = (const float4*)(mb + (size_t)n * K_DIM);
        float s0 = 0.f, s1 = 0.f, s2 = 0.f, s3 = 0.f;
        #pragma unroll 4
        for (int k = 0; k < K_DIM / 4; k++) {
            float4 mv = m4[k], fx = f4[k];
            s0 = fmaf(mv.x, fx.x, s0); s1 = fmaf(mv.y, fx.y, s1);
            s2 = fmaf(mv.z, fx.z, s2); s3 = fmaf(mv.w, fx.w, s3);
        }
        float d = fn + g_mnorm[n] - 2.0f * ((s0 + s1) + (s2 + s3));
        insert9(t, fmaxf(d, 0.0f));
    }
    warp_merge9(t);

    int lane = tid & 31, w = tid >> 5;
    if (lane == 0)
        #pragma unroll
        for (int j = 0; j < TOPK; j++) wt[w][j] = t[j];
    __syncthreads();
    if (tid == 0) {
        float m[TOPK];
        #pragma unroll
        for (int j = 0; j < TOPK; j++) m[j] = wt[0][j];
        for (int w2 = 1; w2 < 4; w2++)
            for (int j = 0; j < TOPK; j++) insert9(m, wt[w2][j]);
        float* dst = g_part + ((size_t)b * NSLICE + slice) * TOPK;
        for (int j = 0; j < TOPK; j++) dst[j] = m[j];
    }
}

__global__ void image_final(float* __restrict__ out_img) {
    int tid = threadIdx.x, w = tid >> 5, lane = tid & 31;
    const float* p = g_part + ((size_t)w * NSLICE + lane) * TOPK;
    float t[TOPK];
    #pragma unroll
    for (int j = 0; j < TOPK; j++) t[j] = p[j];
    warp_merge9(t);
    if (lane == 0) {
        float s[TOPK];
        #pragma unroll
        for (int j = 0; j < TOPK; j++) s[j] = sqrtf(t[j]);
        float mx = s[TOPK - 1];
        float sum = 0.f, e0 = 0.f;
        #pragma unroll
        for (int j = 0; j < TOPK; j++) {
            float e = expf(s[j] - mx);
            sum += e;
            if (j == 0) e0 = e;
        }
        out_img[w] = s[0] * (1.0f - e0 / sum);
    }
}

/* ---------------- host ---------------- */
extern "C" void kernel_launch(void* const* d_in, const int* in_sizes, int n_in,
                              void* d_out, int out_size) {
    const float* fv = (const float*)d_in[0];
    const float* mb = (const float*)d_in[1];
    float* out = (float*)d_out;

    static int configured = 0;
    if (!configured) {
        cudaFuncSetAttribute(gemm_min_kernel,
                             cudaFuncAttributeMaxDynamicSharedMemorySize, SMEM_SIZE);
        configured = 1;
    }

    init_kernel<<<(M_ROWS + 255) / 256, 256>>>();
    int warps = M_ROWS + N_COLS;
    prep_kernel<<<(warps * 32 + 255) / 256, 256>>>(fv, mb);
    gemm_min_kernel<<<M_TILES * N_TILES, THREADS, SMEM_SIZE>>>();
    pixel_kernel<<<NBATCH, 1024>>>(out);
    candidate_kernel<<<NBATCH, 1024>>>();
    exact_cand<<<dim3(NSLICE, CSLOTS, NBATCH), 128>>>(fv, mb);
    argmax_refine<<<1, 32>>>();
    image_partial<<<dim3(NSLICE, NBATCH), 128>>>(fv, mb);
    image_final<<<1, 256>>>(out + M_ROWS);
}

// round 8
// speedup vs baseline: 4.2932x; 1.5411x over previous
#include <cuda_runtime.h>
#include <cuda_bf16.h>
#include <math.h>
#include <stdint.h>

#define M_ROWS 8192
#define N_COLS 16384
#define K_DIM  512
#define BM 128
#define BN 256
#define BK 64
#define THREADS 512
#define TOPK 9
#define NBATCH 8
#define NSLICE 32
#define SLICE_W (N_COLS / NSLICE)
#define M_TILES (M_ROWS / BM)            /* 64 */
#define N_TILES (N_COLS / BN)            /* 64 */
#define KSTAGES (K_DIM / BK)             /* 8 */
#define MAXCAND 1024
#define CSLOTS  32
#define CAND_MARGIN 0.9995f              /* observed err 6.24e-5; 4x safety */

#define A_BYTES (BM * BK * 2)            /* 16384 */
#define B_BYTES (BN * BK * 2)            /* 32768 */
#define SM_A(i)  ((i) * A_BYTES)
#define SM_B(i)  (3 * A_BYTES + (i) * B_BYTES)
#define SM_MN    (3 * A_BYTES + 3 * B_BYTES)   /* 147456 */
#define SMEM_SIZE (SM_MN + BN * 4)

__device__ __align__(16) __nv_bfloat16 g_fb[(size_t)M_ROWS * K_DIM];
__device__ __align__(16) __nv_bfloat16 g_mbb[(size_t)N_COLS * K_DIM];
__device__ float    g_fnorm[M_ROWS];
__device__ float    g_mnorm[N_COLS];
__device__ unsigned g_row_min[M_ROWS];
__device__ float    g_pmax[NBATCH];
__device__ int      g_cand_cnt[NBATCH];
__device__ int      g_cand_row[NBATCH][MAXCAND];
__device__ unsigned g_cand_min[NBATCH][MAXCAND];
__device__ int      g_best[NBATCH];
__device__ float    g_part[NBATCH * NSLICE * TOPK];

/* ---------------- PTX helpers ---------------- */
__device__ __forceinline__ uint32_t smem_u32(const void* p) {
    uint32_t a;
    asm("{ .reg .u64 t; cvta.to.shared.u64 t, %1; cvt.u32.u64 %0, t; }" : "=r"(a) : "l"(p));
    return a;
}
__device__ __forceinline__ void cp_async16(uint32_t dst, const void* src) {
    asm volatile("cp.async.cg.shared.global [%0], [%1], 16;" :: "r"(dst), "l"(src) : "memory");
}
__device__ __forceinline__ void cp_commit() { asm volatile("cp.async.commit_group;" ::: "memory"); }
template <int N> __device__ __forceinline__ void cp_wait() {
    asm volatile("cp.async.wait_group %0;" :: "n"(N) : "memory");
}
__device__ __forceinline__ void ldsm4(uint32_t* r, uint32_t addr) {
    asm volatile("ldmatrix.sync.aligned.m8n8.x4.shared.b16 {%0,%1,%2,%3}, [%4];"
                 : "=r"(r[0]), "=r"(r[1]), "=r"(r[2]), "=r"(r[3]) : "r"(addr));
}
__device__ __forceinline__ void mma16816(float* d, const uint32_t* a, uint32_t b0, uint32_t b1) {
    asm volatile("mma.sync.aligned.m16n8k16.row.col.f32.bf16.bf16.f32 "
                 "{%0,%1,%2,%3}, {%4,%5,%6,%7}, {%8,%9}, {%0,%1,%2,%3};"
                 : "+f"(d[0]), "+f"(d[1]), "+f"(d[2]), "+f"(d[3])
                 : "r"(a[0]), "r"(a[1]), "r"(a[2]), "r"(a[3]), "r"(b0), "r"(b1));
}

/* ---------------- small kernels ---------------- */
__global__ void init_kernel() {
    int i = blockIdx.x * blockDim.x + threadIdx.x;
    if (i < M_ROWS) g_row_min[i] = 0x7f800000u;
    if (i < NBATCH) g_cand_cnt[i] = 0;
    if (i < NBATCH * MAXCAND) g_cand_min[i / MAXCAND][i % MAXCAND] = 0x7f800000u;
}

// one warp per row: fp32 norm + bf16 conversion
__global__ void prep_kernel(const float* __restrict__ fv, const float* __restrict__ mb) {
    int gw   = (blockIdx.x * blockDim.x + threadIdx.x) >> 5;
    int lane = threadIdx.x & 31;
    const float* src; __nv_bfloat16* dst; float* nout;
    if (gw < M_ROWS) {
        src = fv + (size_t)gw * K_DIM; dst = g_fb + (size_t)gw * K_DIM; nout = &g_fnorm[gw];
    } else if (gw < M_ROWS + N_COLS) {
        int r = gw - M_ROWS;
        src = mb + (size_t)r * K_DIM; dst = g_mbb + (size_t)r * K_DIM; nout = &g_mnorm[r];
    } else return;
    float s = 0.f;
    #pragma unroll
    for (int i = lane; i < K_DIM / 4; i += 32) {
        float4 v = ((const float4*)src)[i];
        s += v.x * v.x + v.y * v.y + v.z * v.z + v.w * v.w;
        __nv_bfloat162 lo = __floats2bfloat162_rn(v.x, v.y);
        __nv_bfloat162 hi = __floats2bfloat162_rn(v.z, v.w);
        uint2 pk; pk.x = *(uint32_t*)&lo; pk.y = *(uint32_t*)&hi;
        ((uint2*)dst)[i] = pk;
    }
    #pragma unroll
    for (int o = 16; o; o >>= 1) s += __shfl_xor_sync(0xffffffffu, s, o);
    if (lane == 0) *nout = s;
}

/* ---------------- GEMM + fused row-min (mma.sync bf16) ---------------- */
__device__ __forceinline__ void load_stage(uint32_t sb, int buf,
                                           const __nv_bfloat16* Ap,
                                           const __nv_bfloat16* Bp,
                                           int kc, int tid) {
    uint32_t a0 = sb + SM_A(buf);
    uint32_t b0 = sb + SM_B(buf);
    #pragma unroll
    for (int j = 0; j < 2; j++) {
        int q = tid + j * THREADS, r = q >> 3, c = q & 7;
        uint32_t off = (uint32_t)((r >> 3) * 1024 + (r & 7) * 128 + ((c ^ (r & 7)) << 4));
        cp_async16(a0 + off, Ap + (size_t)r * K_DIM + kc + c * 8);
    }
    #pragma unroll
    for (int j = 0; j < 4; j++) {
        int q = tid + j * THREADS, r = q >> 3, c = q & 7;
        uint32_t off = (uint32_t)((r >> 3) * 1024 + (r & 7) * 128 + ((c ^ (r & 7)) << 4));
        cp_async16(b0 + off, Bp + (size_t)r * K_DIM + kc + c * 8);
    }
    cp_commit();
}

__global__ void __launch_bounds__(THREADS, 1)
gemm_min_kernel() {
    extern __shared__ char smem[];
    uint32_t sb = smem_u32(smem);
    float* mn_s = (float*)(smem + SM_MN);

    const int tid  = threadIdx.x;
    const int lane = tid & 31;
    const int wid  = tid >> 5;
    const int wm   = wid >> 3;
    const int wn   = wid & 7;

    const int tile = blockIdx.x;
    const int mt = tile >> 6;
    const int nt = tile & 63;
    const __nv_bfloat16* Ap = g_fb  + (size_t)mt * BM * K_DIM;
    const __nv_bfloat16* Bp = g_mbb + (size_t)nt * BN * K_DIM;

    if (tid < BN / 2) {
        mn_s[tid * 2]     = g_mnorm[nt * BN + tid * 2];
        mn_s[tid * 2 + 1] = g_mnorm[nt * BN + tid * 2 + 1];
    }

    uint32_t a_base[4], b_base[2];
    uint32_t a_xr, b_xr;
    {
        int rA = wm * 64 + (lane & 15);
        a_xr = (uint32_t)(rA & 7);
        #pragma unroll
        for (int mi = 0; mi < 4; mi++) {
            int r = rA + mi * 16;
            a_base[mi] = (uint32_t)((r >> 3) * 1024 + (r & 7) * 128);
        }
        int rB = wn * 32 + (lane & 7) + ((lane >> 4) << 3);
        b_xr = (uint32_t)(rB & 7);
        #pragma unroll
        for (int nb = 0; nb < 2; nb++) {
            int r = rB + nb * 16;
            b_base[nb] = (uint32_t)((r >> 3) * 1024 + (r & 7) * 128);
        }
    }
    const uint32_t a_csel = (uint32_t)(lane >> 4);
    const uint32_t b_csel = (uint32_t)((lane >> 3) & 1);

    float acc[4][4][4];
    #pragma unroll
    for (int mi = 0; mi < 4; mi++)
        #pragma unroll
        for (int ni = 0; ni < 4; ni++)
            #pragma unroll
            for (int k = 0; k < 4; k++) acc[mi][ni][k] = 0.f;

    load_stage(sb, 0, Ap, Bp, 0, tid);
    load_stage(sb, 1, Ap, Bp, BK, tid);

    #pragma unroll
    for (int s = 0; s < KSTAGES; s++) {
        if (s < KSTAGES - 1) cp_wait<1>(); else cp_wait<0>();
        __syncthreads();                 // orders: prior-iter reads done AND cp.async data visible
        if (s + 2 < KSTAGES)
            load_stage(sb, (s + 2) % 3, Ap, Bp, (s + 2) * BK, tid);

        const int buf = s % 3;
        const uint32_t ab = sb + SM_A(buf);
        const uint32_t bb = sb + SM_B(buf);
        #pragma unroll
        for (int ks = 0; ks < 4; ks++) {
            uint32_t a[4][4], bf[2][4];
            const uint32_t ca = (uint32_t)(ks * 2) + a_csel;
            const uint32_t cb = (uint32_t)(ks * 2) + b_csel;
            #pragma unroll
            for (int mi = 0; mi < 4; mi++)
                ldsm4(a[mi], ab + a_base[mi] + ((ca ^ a_xr) << 4));
            #pragma unroll
            for (int nb = 0; nb < 2; nb++)
                ldsm4(bf[nb], bb + b_base[nb] + ((cb ^ b_xr) << 4));
            #pragma unroll
            for (int mi = 0; mi < 4; mi++)
                #pragma unroll
                for (int ni = 0; ni < 4; ni++)
                    mma16816(acc[mi][ni], a[mi], bf[ni >> 1][(ni & 1) * 2],
                             bf[ni >> 1][(ni & 1) * 2 + 1]);
        }
    }

    const int q  = lane & 3;
    const int gr = lane >> 2;
    #pragma unroll
    for (int mi = 0; mi < 4; mi++) {
        #pragma unroll
        for (int h = 0; h < 2; h++) {
            float vmin = 3.402823e38f;
            #pragma unroll
            for (int ni = 0; ni < 4; ni++) {
                int col = wn * 32 + ni * 8 + q * 2;
                float v0 = fmaf(-2.0f, acc[mi][ni][h * 2],     mn_s[col]);
                float v1 = fmaf(-2.0f, acc[mi][ni][h * 2 + 1], mn_s[col + 1]);
                vmin = fminf(vmin, fminf(v0, v1));
            }
            vmin = fminf(vmin, __shfl_xor_sync(0xffffffffu, vmin, 1));
            vmin = fminf(vmin, __shfl_xor_sync(0xffffffffu, vmin, 2));
            if (q == 0) {
                int row = mt * BM + wm * 64 + mi * 16 + h * 8 + gr;
                float d = fmaxf(g_fnorm[row] + vmin, 0.0f);
                atomicMin(&g_row_min[row], __float_as_uint(d));
            }
        }
    }
}

/* ---------------- tails ---------------- */
__global__ void pixel_kernel(float* __restrict__ out_pixel) {
    __shared__ float sv[1024];
    int b = blockIdx.x, i = threadIdx.x;
    int r = b * 1024 + i;
    float v = sqrtf(__uint_as_float(g_row_min[r]));
    out_pixel[r] = v;
    sv[i] = v;
    __syncthreads();
    for (int s = 512; s > 0; s >>= 1) {
        if (i < s) sv[i] = fmaxf(sv[i], sv[i + s]);
        __syncthreads();
    }
    if (i == 0) g_pmax[b] = sv[0];
}

__global__ void candidate_kernel() {
    int b = blockIdx.x, i = threadIdx.x;
    int r = b * 1024 + i;
    float v = sqrtf(__uint_as_float(g_row_min[r]));
    if (v >= g_pmax[b] * CAND_MARGIN) {
        int slot = atomicAdd(&g_cand_cnt[b], 1);
        g_cand_row[b][slot] = r;       // slot < 1024 always
    }
}

// exact fp32 min distance per candidate
__global__ void exact_cand(const float* __restrict__ fv, const float* __restrict__ mb) {
    int slice = blockIdx.x, cslot = blockIdx.y, b = blockIdx.z;
    int cnt = g_cand_cnt[b];
    if (cnt > MAXCAND) cnt = MAXCAND;
    __shared__ float f[K_DIM];
    __shared__ float wmin[4];
    int tid = threadIdx.x;

    for (int c = cslot; c < cnt; c += CSLOTS) {
        int row = g_cand_row[b][c];
        __syncthreads();
        for (int i = tid; i < K_DIM; i += 128) f[i] = fv[(size_t)row * K_DIM + i];
        __syncthreads();
        float fn = g_fnorm[row];

        int n0 = slice * SLICE_W + tid;
        const float* m0 = mb + (size_t)n0 * K_DIM;
        const float* m1 = m0 + (size_t)128 * K_DIM;
        const float* m2 = m1 + (size_t)128 * K_DIM;
        const float* m3 = m2 + (size_t)128 * K_DIM;
        float a0 = 0.f, a1 = 0.f, a2 = 0.f, a3 = 0.f;
        for (int k = 0; k < K_DIM; k++) {
            float fk = f[k];
            a0 = fmaf(fk, __ldg(m0 + k), a0);
            a1 = fmaf(fk, __ldg(m1 + k), a1);
            a2 = fmaf(fk, __ldg(m2 + k), a2);
            a3 = fmaf(fk, __ldg(m3 + k), a3);
        }
        float d0 = fmaxf(fn + g_mnorm[n0]       - 2.0f * a0, 0.0f);
        float d1 = fmaxf(fn + g_mnorm[n0 + 128] - 2.0f * a1, 0.0f);
        float d2 = fmaxf(fn + g_mnorm[n0 + 256] - 2.0f * a2, 0.0f);
        float d3 = fmaxf(fn + g_mnorm[n0 + 384] - 2.0f * a3, 0.0f);
        float vmin = fminf(fminf(d0, d1), fminf(d2, d3));

        #pragma unroll
        for (int o = 16; o; o >>= 1)
            vmin = fminf(vmin, __shfl_xor_sync(0xffffffffu, vmin, o));
        if ((tid & 31) == 0) wmin[tid >> 5] = vmin;
        __syncthreads();
        if (tid == 0) {
            float m = fminf(fminf(wmin[0], wmin[1]), fminf(wmin[2], wmin[3]));
            atomicMin(&g_cand_min[b][c], __float_as_uint(m));
        }
    }
}

// exact argmax over candidates (first-index tie-break)
__global__ void argmax_refine() {
    int b = threadIdx.x;
    if (b >= NBATCH) return;
    int cnt = g_cand_cnt[b];
    if (cnt > MAXCAND) cnt = MAXCAND;
    float best_v = -1.f;
    int best_r = 0x7fffffff;
    for (int c = 0; c < cnt; c++) {
        float v = sqrtf(__uint_as_float(g_cand_min[b][c]));
        int r = g_cand_row[b][c];
        if (v > best_v || (v == best_v && r < best_r)) { best_v = v; best_r = r; }
    }
    g_best[b] = best_r;
}

__device__ __forceinline__ void insert9(float* t, float v) {
    if (v < t[TOPK - 1]) {
        t[TOPK - 1] = v;
        #pragma unroll
        for (int j = TOPK - 1; j > 0; j--)
            if (t[j] < t[j - 1]) { float tmp = t[j]; t[j] = t[j - 1]; t[j - 1] = tmp; }
    }
}

// snapshot-then-insert warp merge (order matters: do NOT interleave shfl/insert)
__device__ __forceinline__ void warp_merge9(float* t) {
    #pragma unroll
    for (int off = 1; off < 32; off <<= 1) {
        float o[TOPK];
        #pragma unroll
        for (int j = 0; j < TOPK; j++) o[j] = __shfl_xor_sync(0xffffffffu, t[j], off);
        #pragma unroll
        for (int j = 0; j < TOPK; j++) insert9(t, o[j]);
    }
}

__global__ void image_partial(const float* __restrict__ fv, const float* __restrict__ mb) {
    __shared__ float f[K_DIM];
    __shared__ float wt[4][TOPK];
    int slice = blockIdx.x, b = blockIdx.y;
    int tid = threadIdx.x;
    int row = g_best[b];
    for (int i = tid; i < K_DIM; i += 128) f[i] = fv[(size_t)row * K_DIM + i];
    __syncthreads();
    float fn = g_fnorm[row];

    float t[TOPK];
    #pragma unroll
    for (int j = 0; j < TOPK; j++) t[j] = 3.402823e38f;

    const float4* f4 = (const float4*)f;
    for (int nl = tid; nl < SLICE_W; nl += 128) {
        int n = slice * SLICE_W + nl;
        const float4* m4 = (const float4*)(mb + (size_t)n * K_DIM);
        float s0 = 0.f, s1 = 0.f, s2 = 0.f, s3 = 0.f;
        #pragma unroll 4
        for (int k = 0; k < K_DIM / 4; k++) {
            float4 mv = m4[k], fx = f4[k];
            s0 = fmaf(mv.x, fx.x, s0); s1 = fmaf(mv.y, fx.y, s1);
            s2 = fmaf(mv.z, fx.z, s2); s3 = fmaf(mv.w, fx.w, s3);
        }
        float d = fn + g_mnorm[n] - 2.0f * ((s0 + s1) + (s2 + s3));
        insert9(t, fmaxf(d, 0.0f));
    }
    warp_merge9(t);

    int lane = tid & 31, w = tid >> 5;
    if (lane == 0)
        #pragma unroll
        for (int j = 0; j < TOPK; j++) wt[w][j] = t[j];
    __syncthreads();
    if (tid == 0) {
        float m[TOPK];
        #pragma unroll
        for (int j = 0; j < TOPK; j++) m[j] = wt[0][j];
        for (int w2 = 1; w2 < 4; w2++)
            for (int j = 0; j < TOPK; j++) insert9(m, wt[w2][j]);
        float* dst = g_part + ((size_t)b * NSLICE + slice) * TOPK;
        for (int j = 0; j < TOPK; j++) dst[j] = m[j];
    }
}

__global__ void image_final(float* __restrict__ out_img) {
    int tid = threadIdx.x, w = tid >> 5, lane = tid & 31;
    const float* p = g_part + ((size_t)w * NSLICE + lane) * TOPK;
    float t[TOPK];
    #pragma unroll
    for (int j = 0; j < TOPK; j++) t[j] = p[j];
    warp_merge9(t);
    if (lane == 0) {
        float s[TOPK];
        #pragma unroll
        for (int j = 0; j < TOPK; j++) s[j] = sqrtf(t[j]);
        float mx = s[TOPK - 1];
        float sum = 0.f, e0 = 0.f;
        #pragma unroll
        for (int j = 0; j < TOPK; j++) {
            float e = expf(s[j] - mx);
            sum += e;
            if (j == 0) e0 = e;
        }
        out_img[w] = s[0] * (1.0f - e0 / sum);
    }
}

/* ---------------- host ---------------- */
extern "C" void kernel_launch(void* const* d_in, const int* in_sizes, int n_in,
                              void* d_out, int out_size) {
    const float* fv = (const float*)d_in[0];
    const float* mb = (const float*)d_in[1];
    float* out = (float*)d_out;

    static int configured = 0;
    if (!configured) {
        cudaFuncSetAttribute(gemm_min_kernel,
                             cudaFuncAttributeMaxDynamicSharedMemorySize, SMEM_SIZE);
        configured = 1;
    }

    init_kernel<<<(M_ROWS + 255) / 256, 256>>>();
    int warps = M_ROWS + N_COLS;
    prep_kernel<<<(warps * 32 + 255) / 256, 256>>>(fv, mb);
    gemm_min_kernel<<<M_TILES * N_TILES, THREADS, SMEM_SIZE>>>();
    pixel_kernel<<<NBATCH, 1024>>>(out);
    candidate_kernel<<<NBATCH, 1024>>>();
    exact_cand<<<dim3(NSLICE, CSLOTS, NBATCH), 128>>>(fv, mb);
    argmax_refine<<<1, 32>>>();
    image_partial<<<dim3(NSLICE, NBATCH), 128>>>(fv, mb);
    image_final<<<1, 256>>>(out + M_ROWS);
}